// round 1
// baseline (speedup 1.0000x reference)
#include <cuda_runtime.h>
#include <cuda_bf16.h>

// y[b,n] = x[b,n] * W[n],  W[n] = sum over valid frames m of aw[j]*sw[j],
// j = (n mod 256) + 256*m, m in [max(0, q-8188), min(3, q)], q = n/256.
// Interior (3 <= q <= 8188): full 4-term sum, depends only on n mod 256.

#define HOPC      256u
#define SEGC      1024u
#define NSAMP     (1u << 21)          // samples per row
#define NROWS     16u
#define QMAXV     8188u               // num_segments - 1
#define TOTAL4    ((NROWS * NSAMP) / 4u)

__global__ void __launch_bounds__(256)
segmenter_roundtrip_kernel(const float4* __restrict__ x,
                           const float*  __restrict__ aw,
                           const float*  __restrict__ sw,
                           float4*       __restrict__ y) {
    const unsigned tid = threadIdx.x;
    // Per-thread lane phase r = (4*tid) mod 256 — invariant across the
    // grid-stride loop because the stride (grid*1024 samples) is a
    // multiple of 256.
    const unsigned r = (tid << 2) & (HOPC - 1u);

    // Interior weights for this thread's 4 lanes (registers; windows are
    // tiny and L1/L2-hot, so these 32 loads are negligible).
    float w0 = 0.f, w1 = 0.f, w2 = 0.f, w3 = 0.f;
#pragma unroll
    for (int m = 0; m < 4; ++m) {
        const unsigned j = r + (unsigned)m * HOPC;
        w0 += aw[j + 0] * sw[j + 0];
        w1 += aw[j + 1] * sw[j + 1];
        w2 += aw[j + 2] * sw[j + 2];
        w3 += aw[j + 3] * sw[j + 3];
    }

    const unsigned stride = gridDim.x * blockDim.x;
    for (unsigned i = blockIdx.x * blockDim.x + tid; i < TOTAL4; i += stride) {
        float4 v = x[i];
        const unsigned n = (i << 2) & (NSAMP - 1u);   // sample index within row
        const unsigned q = n >> 8;                    // frame-phase index

        if (q >= 3u && q <= QMAXV) {
            // Interior fast path (99.66% of elements)
            v.x *= w0; v.y *= w1; v.z *= w2; v.w *= w3;
        } else {
            // Boundary: truncated frame sum. All 4 lanes of this float4
            // share q (groups of 4 never straddle a 256 boundary).
            const int m_lo = (q > QMAXV) ? (int)(q - QMAXV) : 0;
            const int m_hi = (q < 3u) ? (int)q : 3;
            float a0 = 0.f, a1 = 0.f, a2 = 0.f, a3 = 0.f;
            for (int m = m_lo; m <= m_hi; ++m) {
                const unsigned j = r + (unsigned)m * HOPC;
                a0 += aw[j + 0] * sw[j + 0];
                a1 += aw[j + 1] * sw[j + 1];
                a2 += aw[j + 2] * sw[j + 2];
                a3 += aw[j + 3] * sw[j + 3];
            }
            v.x *= a0; v.y *= a1; v.z *= a2; v.w *= a3;
        }
        y[i] = v;
    }
}

extern "C" void kernel_launch(void* const* d_in, const int* in_sizes, int n_in,
                              void* d_out, int out_size) {
    const float4* x  = (const float4*)d_in[0];
    const float*  aw = (const float*)d_in[1];
    const float*  sw = (const float*)d_in[2];
    float4*       y  = (float4*)d_out;

    (void)in_sizes; (void)n_in; (void)out_size;

    // 4096 blocks x 256 threads: 8 float4 per thread, plenty of MLP for
    // the HBM stream, weight precompute amortized 8x.
    segmenter_roundtrip_kernel<<<4096, 256>>>(x, aw, sw, y);
}

// round 2
// speedup vs baseline: 1.0894x; 1.0894x over previous
#include <cuda_runtime.h>
#include <cuda_bf16.h>

// y[b,n] = x[b,n] * W[n],  W[n] = sum over valid frames m of aw[j]*sw[j],
// j = (n mod 256) + 256*m, m in [max(0, q-8188), min(3, q)], q = n/256.
// Interior (3 <= q <= 8188): full 4-term sum, depends only on n mod 256.

#define HOPC      256u
#define NSAMP     (1u << 21)          // samples per row
#define NROWS     16u
#define QMAXV     8188u               // num_segments - 1
#define TOTAL4    ((NROWS * NSAMP) / 4u)   // 8,388,608 float4
#define NBLK      4096u
#define NTHR      256u
#define PER_THREAD 8u                 // TOTAL4 / (NBLK*NTHR) exactly

__global__ void __launch_bounds__(NTHR)
segmenter_roundtrip_kernel(const float4* __restrict__ x,
                           const float*  __restrict__ aw,
                           const float*  __restrict__ sw,
                           float4*       __restrict__ y) {
    const unsigned tid = threadIdx.x;
    // Lane phase r = (4*tid) mod 256 — invariant across iterations because
    // the stride (NBLK*NTHR*4 samples) is a multiple of 256.
    const unsigned r = (tid << 2) & (HOPC - 1u);

    // Interior weights (registers; windows are L1/L2-hot).
    float w0 = 0.f, w1 = 0.f, w2 = 0.f, w3 = 0.f;
#pragma unroll
    for (int m = 0; m < 4; ++m) {
        const unsigned j = r + (unsigned)m * HOPC;
        w0 += aw[j + 0] * sw[j + 0];
        w1 += aw[j + 1] * sw[j + 1];
        w2 += aw[j + 2] * sw[j + 2];
        w3 += aw[j + 3] * sw[j + 3];
    }

    const unsigned base   = blockIdx.x * NTHR + tid;
    const unsigned stride = NBLK * NTHR;

    // ---- Front-batch all 8 loads: MLP = 8 per thread ----
    float4 v[PER_THREAD];
#pragma unroll
    for (unsigned k = 0; k < PER_THREAD; ++k) {
        v[k] = __ldcs(&x[base + k * stride]);
    }

    // ---- Scale + store ----
#pragma unroll
    for (unsigned k = 0; k < PER_THREAD; ++k) {
        const unsigned i = base + k * stride;
        const unsigned n = (i << 2) & (NSAMP - 1u);   // sample index in row
        const unsigned q = n >> 8;                    // frame-phase index

        float4 t = v[k];
        if (q >= 3u && q <= QMAXV) {
            // Interior fast path (99.66% of elements)
            t.x *= w0; t.y *= w1; t.z *= w2; t.w *= w3;
        } else {
            // Boundary: truncated frame sum (windows are L2-hot).
            const int m_lo = (q > QMAXV) ? (int)(q - QMAXV) : 0;
            const int m_hi = (q < 3u) ? (int)q : 3;
            float a0 = 0.f, a1 = 0.f, a2 = 0.f, a3 = 0.f;
            for (int m = m_lo; m <= m_hi; ++m) {
                const unsigned j = r + (unsigned)m * HOPC;
                a0 += aw[j + 0] * sw[j + 0];
                a1 += aw[j + 1] * sw[j + 1];
                a2 += aw[j + 2] * sw[j + 2];
                a3 += aw[j + 3] * sw[j + 3];
            }
            t.x *= a0; t.y *= a1; t.z *= a2; t.w *= a3;
        }
        __stcs(&y[i], t);
    }
}

extern "C" void kernel_launch(void* const* d_in, const int* in_sizes, int n_in,
                              void* d_out, int out_size) {
    const float4* x  = (const float4*)d_in[0];
    const float*  aw = (const float*)d_in[1];
    const float*  sw = (const float*)d_in[2];
    float4*       y  = (float4*)d_out;

    (void)in_sizes; (void)n_in; (void)out_size;

    segmenter_roundtrip_kernel<<<NBLK, NTHR>>>(x, aw, sw, y);
}